// round 15
// baseline (speedup 1.0000x reference)
#include <cuda_runtime.h>
#include <cuda_bf16.h>
#include <cstdint>

#define NN 20000
#define EE 256000
#define HD 128
#define NRR 100

// ---------------- scratch (static device globals; no allocation) ----------------
__device__ float g_agg1[NN * HD];      // layer1 aggregation (plain stores, CSR)
__device__ float g_tmp1[NN * HD];      // x0 @ lw1 + b1
__device__ float g_out1[NN * HD];      // layer1 output (relu)
__device__ float g_agg2[NN * 2 * HD];  // layer2 aggregation (plain stores, CSR)
__device__ float g_tmp2[NN * 2 * HD];  // out1 @ lw2 + b2
__device__ float g_z[NN * HD];         // sampled latent (fp32, for hr gather)
__device__ __nv_bfloat16 g_zhi[NN * HD];
__device__ __nv_bfloat16 g_zlo[NN * HD];
__device__ __nv_bfloat16 g_hrhi[2048 * HD];
__device__ __nv_bfloat16 g_hrlo[2048 * HD];
__device__ int   g_cnt[NN];            // dst histogram (zero at load; re-zeroed by scan)
__device__ int   g_off[NN + 1];        // dst CSR offsets
__device__ int   g_cur[NN];            // scatter cursors
__device__ int4  g_recs[EE];           // dst-sorted records {src, rel, norm, hsrc}

// ---------------- helpers ----------------
__device__ __forceinline__ unsigned long long pk2(float x, float y) {
    unsigned long long r;
    asm("mov.b64 %0, {%1, %2};" : "=l"(r) : "f"(x), "f"(y));
    return r;
}
__device__ __forceinline__ void upk2(unsigned long long p, float& x, float& y) {
    asm("mov.b64 {%0, %1}, %2;" : "=f"(x), "=f"(y) : "l"(p));
}
__device__ __forceinline__ void fma2(unsigned long long& d, unsigned long long a, unsigned long long b) {
    asm("fma.rn.f32x2 %0, %1, %2, %0;" : "+l"(d) : "l"(a), "l"(b));
}
__device__ __forceinline__ float softplus_f(float x) {
    return fmaxf(x, 0.f) + log1pf(expf(-fabsf(x)));
}
__device__ __forceinline__ uint32_t smem_to_u32(const void* p) {
    uint32_t a;
    asm("{ .reg .u64 t; cvta.to.shared.u64 t, %1; cvt.u32.u64 %0, t; }" : "=r"(a) : "l"(p));
    return a;
}
__device__ __forceinline__ void ldm_x4(uint32_t& r0, uint32_t& r1, uint32_t& r2, uint32_t& r3,
                                       uint32_t addr) {
    asm volatile("ldmatrix.sync.aligned.m8n8.x4.shared.b16 {%0,%1,%2,%3}, [%4];"
                 : "=r"(r0), "=r"(r1), "=r"(r2), "=r"(r3) : "r"(addr));
}
__device__ __forceinline__ void ldm_x2(uint32_t& r0, uint32_t& r1, uint32_t addr) {
    asm volatile("ldmatrix.sync.aligned.m8n8.x2.shared.b16 {%0,%1}, [%2];"
                 : "=r"(r0), "=r"(r1) : "r"(addr));
}
__device__ __forceinline__ void mma_bf16(float* c, uint32_t a0, uint32_t a1, uint32_t a2,
                                         uint32_t a3, uint32_t b0, uint32_t b1) {
    asm volatile(
        "mma.sync.aligned.m16n8k16.row.col.f32.bf16.bf16.f32 "
        "{%0,%1,%2,%3}, {%4,%5,%6,%7}, {%8,%9}, {%0,%1,%2,%3};"
        : "+f"(c[0]), "+f"(c[1]), "+f"(c[2]), "+f"(c[3])
        : "r"(a0), "r"(a1), "r"(a2), "r"(a3), "r"(b0), "r"(b1));
}

// ---------------- sort A: dst histogram ----------------
__global__ __launch_bounds__(256) void hist_kernel(const int* __restrict__ dst) {
    int e = blockIdx.x * 256 + threadIdx.x;
    atomicAdd(&g_cnt[dst[e]], 1);
}

// ---------------- sort B: CSR offsets over 20000 dst bins; re-zero cnt ----------------
__global__ __launch_bounds__(1024) void scan_kernel() {
    __shared__ int part[1024];
    int t = threadIdx.x;
    int base = t * 20;
    int loc[20];
    int sum = 0;
#pragma unroll
    for (int k = 0; k < 20; k++) {
        int i = base + k;
        int c = (i < NN) ? g_cnt[i] : 0;
        loc[k] = sum;
        sum += c;
    }
    part[t] = sum;
    __syncthreads();
#pragma unroll
    for (int d = 1; d < 1024; d <<= 1) {
        int v = (t >= d) ? part[t - d] : 0;
        __syncthreads();
        part[t] += v;
        __syncthreads();
    }
    int pref = t ? part[t - 1] : 0;
#pragma unroll
    for (int k = 0; k < 20; k++) {
        int i = base + k;
        if (i < NN) {
            int o = pref + loc[k];
            g_off[i] = o;
            g_cur[i] = o;
            g_cnt[i] = 0;   // ready for next replay
        }
    }
    if (t == 1023) g_off[NN] = part[1023];
}

// ---------------- sort C: scatter into dst-CSR; precompute h[src] ----------------
__global__ __launch_bounds__(256) void scatter_kernel(const int* __restrict__ src,
                                                      const int* __restrict__ dst,
                                                      const int* __restrict__ et,
                                                      const float* __restrict__ norm,
                                                      const int* __restrict__ h) {
    int e = blockIdx.x * 256 + threadIdx.x;
    int s = src[e];
    int d = dst[e];
    int pos = atomicAdd(&g_cur[d], 1);
    g_recs[pos] = make_int4(s, et[e], __float_as_int(norm[e]), h[s]);
}

// ---------------- layer1 edges: warp per dst, register accumulation, NO atomics --------
// lane l owns bdd blocks 2l,2l+1 -> out cols 4l..4l+3. W1 (100KB) stays L1-hot via __ldg;
// x + recs bypass L1 via __ldcg.
__global__ __launch_bounds__(256) void edge1_kernel(const float* __restrict__ W1,
                                                    const float* __restrict__ embed) {
    int d = (blockIdx.x * 256 + threadIdx.x) >> 5;   // 0..19999 exact
    int lane = threadIdx.x & 31;
    int s0 = __ldg(&g_off[d]), s1 = __ldg(&g_off[d + 1]);
    float a0 = 0.f, a1 = 0.f, a2 = 0.f, a3 = 0.f;
    if (s0 < s1) {
        int4 rec = __ldcg(&g_recs[s0]);
#pragma unroll 1
        for (int i = s0; i < s1; i++) {
            int4 nrec = (i + 1 < s1) ? __ldcg(&g_recs[i + 1]) : rec;
            float4 xv = __ldcg((const float4*)(embed + rec.w * HD) + lane);
            const float4* w4 = (const float4*)(W1 + rec.y * 256 + lane * 8);
            float4 wa = __ldg(w4), wb = __ldg(w4 + 1);
            float nrm = __int_as_float(rec.z);
            a0 += (xv.x * wa.x + xv.y * wa.z) * nrm;
            a1 += (xv.x * wa.y + xv.y * wa.w) * nrm;
            a2 += (xv.z * wb.x + xv.w * wb.z) * nrm;
            a3 += (xv.z * wb.y + xv.w * wb.w) * nrm;
            rec = nrec;
        }
    }
    ((float4*)(g_agg1 + d * HD))[lane] = make_float4(a0, a1, a2, a3);
}

// ---------------- sl1 GEMM: tmp1 = embed[h] @ lw1 + b1 (overlaps sort) ----------------
__global__ __launch_bounds__(256) void sl1gemm_kernel(const float* __restrict__ lw1,
                                                      const float* __restrict__ b1,
                                                      const int* __restrict__ h,
                                                      const float* __restrict__ embed) {
    __shared__ float4 ws4[32][32];
    __shared__ float xsh[8][4][33];
    int tid = threadIdx.x;
    int w = tid >> 5, lane = tid & 31;
    int row0 = blockIdx.x * 32 + w * 4;
    int hr_[4];
#pragma unroll
    for (int j = 0; j < 4; j++) hr_[j] = __ldg(&h[row0 + j]);
    unsigned long long acc[4][2];
#pragma unroll
    for (int j = 0; j < 4; j++) { acc[j][0] = 0ULL; acc[j][1] = 0ULL; }
    const float4* lw4 = (const float4*)lw1;
    for (int kc = 0; kc < 4; kc++) {
#pragma unroll
        for (int it = 0; it < 4; it++) {
            int idx = tid + it * 256;
            int k = idx >> 5, c = idx & 31;
            ws4[k][c] = lw4[(kc * 32 + k) * 32 + c];
        }
#pragma unroll
        for (int j = 0; j < 4; j++)
            xsh[w][j][lane] = embed[hr_[j] * HD + kc * 32 + lane];
        __syncthreads();
#pragma unroll
        for (int k = 0; k < 32; k++) {
            float4 wv = ws4[k][lane];
            unsigned long long wlo = pk2(wv.x, wv.y), whi = pk2(wv.z, wv.w);
#pragma unroll
            for (int j = 0; j < 4; j++) {
                float xv = xsh[w][j][k];
                unsigned long long x2 = pk2(xv, xv);
                fma2(acc[j][0], x2, wlo);
                fma2(acc[j][1], x2, whi);
            }
        }
        __syncthreads();
    }
    float4 bv = ((const float4*)b1)[lane];
#pragma unroll
    for (int j = 0; j < 4; j++) {
        float o0, o1, o2, o3;
        upk2(acc[j][0], o0, o1);
        upk2(acc[j][1], o2, o3);
        ((float4*)(g_tmp1 + (row0 + j) * HD))[lane] =
            make_float4(o0 + bv.x, o1 + bv.y, o2 + bv.z, o3 + bv.w);
    }
}

// ---------------- sl1 epilogue: out1 = relu(agg1 + tmp1) ----------------
__global__ __launch_bounds__(256) void sl1epi_kernel() {
    int idx = blockIdx.x * 256 + threadIdx.x;   // float4 index
    float4 a = ((const float4*)g_agg1)[idx];
    float4 t = ((const float4*)g_tmp1)[idx];
    ((float4*)g_out1)[idx] = make_float4(fmaxf(a.x + t.x, 0.f), fmaxf(a.y + t.y, 0.f),
                                         fmaxf(a.z + t.z, 0.f), fmaxf(a.w + t.w, 0.f));
}

// ---------------- layer2 edges: persistent, W2 (200KB) in SMEM, warp per dst ------------
// lane l owns blocks 2l,2l+1 -> out cols 8l..8l+7. x via __ldcg; one plain store per dst.
#define E2_BLOCKS 148
#define E2_THREADS 512
#define E2_W2FLOATS (NRR * 512)            // 51200 floats = 204800 B

__global__ __launch_bounds__(E2_THREADS, 1) void edge2_kernel(const float* __restrict__ W2) {
    extern __shared__ float w2s[];
    for (int i = threadIdx.x; i < E2_W2FLOATS / 4; i += E2_THREADS)
        ((float4*)w2s)[i] = ((const float4*)W2)[i];
    __syncthreads();
    int gw = blockIdx.x * (E2_THREADS / 32) + (threadIdx.x >> 5);
    int lane = threadIdx.x & 31;
    const int NW = E2_BLOCKS * (E2_THREADS / 32);
#pragma unroll 1
    for (int d = gw; d < NN; d += NW) {
        int s0 = __ldg(&g_off[d]), s1 = __ldg(&g_off[d + 1]);
        float c0 = 0.f, c1 = 0.f, c2 = 0.f, c3 = 0.f;
        float c4 = 0.f, c5 = 0.f, c6 = 0.f, c7 = 0.f;
        if (s0 < s1) {
            int4 rec = __ldcg(&g_recs[s0]);
#pragma unroll 1
            for (int i = s0; i < s1; i++) {
                int4 nrec = (i + 1 < s1) ? __ldcg(&g_recs[i + 1]) : rec;
                float4 xv = __ldcg((const float4*)(g_out1 + rec.x * HD) + lane);
                const float4* wp = (const float4*)(w2s + rec.y * 512 + lane * 16);
                float4 wA = wp[0], wB = wp[1], wC = wp[2], wD = wp[3];
                float nrm = __int_as_float(rec.z);
                c0 += (xv.x * wA.x + xv.y * wB.x) * nrm;
                c1 += (xv.x * wA.y + xv.y * wB.y) * nrm;
                c2 += (xv.x * wA.z + xv.y * wB.z) * nrm;
                c3 += (xv.x * wA.w + xv.y * wB.w) * nrm;
                c4 += (xv.z * wC.x + xv.w * wD.x) * nrm;
                c5 += (xv.z * wC.y + xv.w * wD.y) * nrm;
                c6 += (xv.z * wC.z + xv.w * wD.z) * nrm;
                c7 += (xv.z * wC.w + xv.w * wD.w) * nrm;
                rec = nrec;
            }
        }
        float4* base = (float4*)(g_agg2 + d * 2 * HD);
        base[lane * 2]     = make_float4(c0, c1, c2, c3);
        base[lane * 2 + 1] = make_float4(c4, c5, c6, c7);
    }
}

// ---------------- sl2 GEMM: tmp2 = out1 @ lw2 + b2 (overlaps edge2) ----------------
__global__ __launch_bounds__(256) void sl2gemm_kernel(const float* __restrict__ lw2,
                                                      const float* __restrict__ b2) {
    __shared__ float4 ws4[32][64];
    __shared__ float xsh[8][4][33];
    int tid = threadIdx.x;
    int w = tid >> 5, lane = tid & 31;
    int row0 = blockIdx.x * 32 + w * 4;
    unsigned long long acc[4][4];
#pragma unroll
    for (int j = 0; j < 4; j++)
#pragma unroll
        for (int g = 0; g < 4; g++) acc[j][g] = 0ULL;
    const float4* lw4 = (const float4*)lw2;
    for (int kc = 0; kc < 4; kc++) {
#pragma unroll
        for (int it = 0; it < 8; it++) {
            int idx = tid + it * 256;
            int k = idx >> 6, c = idx & 63;
            ws4[k][c] = lw4[(kc * 32 + k) * 64 + c];
        }
#pragma unroll
        for (int j = 0; j < 4; j++)
            xsh[w][j][lane] = g_out1[(row0 + j) * HD + kc * 32 + lane];
        __syncthreads();
#pragma unroll
        for (int k = 0; k < 32; k++) {
            float4 w0 = ws4[k][lane];
            float4 w1 = ws4[k][32 + lane];
            unsigned long long wl0 = pk2(w0.x, w0.y), wh0 = pk2(w0.z, w0.w);
            unsigned long long wl1 = pk2(w1.x, w1.y), wh1 = pk2(w1.z, w1.w);
#pragma unroll
            for (int j = 0; j < 4; j++) {
                float xv = xsh[w][j][k];
                unsigned long long x2 = pk2(xv, xv);
                fma2(acc[j][0], x2, wl0);
                fma2(acc[j][1], x2, wh0);
                fma2(acc[j][2], x2, wl1);
                fma2(acc[j][3], x2, wh1);
            }
        }
        __syncthreads();
    }
    float4 b0 = ((const float4*)b2)[lane];
    float4 b1v = ((const float4*)b2)[32 + lane];
#pragma unroll
    for (int j = 0; j < 4; j++) {
        int row = row0 + j;
        float m0, m1, m2, m3, v0, v1, v2, v3;
        upk2(acc[j][0], m0, m1);
        upk2(acc[j][1], m2, m3);
        upk2(acc[j][2], v0, v1);
        upk2(acc[j][3], v2, v3);
        ((float4*)(g_tmp2 + row * 2 * HD))[lane] =
            make_float4(m0 + b0.x, m1 + b0.y, m2 + b0.z, m3 + b0.w);
        ((float4*)(g_tmp2 + row * 2 * HD))[32 + lane] =
            make_float4(v0 + b1v.x, v1 + b1v.y, v2 + b1v.z, v3 + b1v.w);
    }
}

// ---------------- sl2 epilogue: z = m + sqrt(softplus(v)+1e-8)*eps, + bf16 split --------
__global__ __launch_bounds__(256) void sl2epi_kernel(const float* __restrict__ eps) {
    int gid = blockIdx.x * 256 + threadIdx.x;   // 0 .. NN*32-1
    int row = gid >> 5, lane = gid & 31;
    float4 m = ((const float4*)(g_tmp2 + row * 2 * HD))[lane];
    float4 hv = ((const float4*)(g_tmp2 + row * 2 * HD))[32 + lane];
    float4 am = ((const float4*)(g_agg2 + row * 2 * HD))[lane];
    float4 av = ((const float4*)(g_agg2 + row * 2 * HD))[32 + lane];
    float4 ev = ((const float4*)(eps + row * HD))[lane];
    float m0 = m.x + am.x, m1 = m.y + am.y, m2 = m.z + am.z, m3 = m.w + am.w;
    float v0 = hv.x + av.x, v1 = hv.y + av.y, v2 = hv.z + av.z, v3 = hv.w + av.w;
    float z0 = m0 + sqrtf(softplus_f(v0) + 1e-8f) * ev.x;
    float z1 = m1 + sqrtf(softplus_f(v1) + 1e-8f) * ev.y;
    float z2 = m2 + sqrtf(softplus_f(v2) + 1e-8f) * ev.z;
    float z3 = m3 + sqrtf(softplus_f(v3) + 1e-8f) * ev.w;
    ((float4*)(g_z + row * HD))[lane] = make_float4(z0, z1, z2, z3);
    __nv_bfloat16 h0b = __float2bfloat16(z0), h1b = __float2bfloat16(z1);
    __nv_bfloat16 h2b = __float2bfloat16(z2), h3b = __float2bfloat16(z3);
    __nv_bfloat16 l0b = __float2bfloat16(z0 - __bfloat162float(h0b));
    __nv_bfloat16 l1b = __float2bfloat16(z1 - __bfloat162float(h1b));
    __nv_bfloat16 l2b = __float2bfloat16(z2 - __bfloat162float(h2b));
    __nv_bfloat16 l3b = __float2bfloat16(z3 - __bfloat162float(h3b));
    __nv_bfloat162* zh = (__nv_bfloat162*)(g_zhi + row * HD);
    __nv_bfloat162* zl = (__nv_bfloat162*)(g_zlo + row * HD);
    zh[lane * 2]     = __nv_bfloat162(h0b, h1b);
    zh[lane * 2 + 1] = __nv_bfloat162(h2b, h3b);
    zl[lane * 2]     = __nv_bfloat162(l0b, l1b);
    zl[lane * 2 + 1] = __nv_bfloat162(l2b, l3b);
}

// ---------------- hr = z[head_ids] * w_rel[rel_ids], split to bf16 hi/lo ----------------
__global__ __launch_bounds__(256) void hr_kernel(const int* __restrict__ head_ids,
                                                 const int* __restrict__ rel_ids,
                                                 const float* __restrict__ w_rel) {
    int idx = blockIdx.x * blockDim.x + threadIdx.x;  // 0 .. 2048*128-1
    int b = idx >> 7, c = idx & 127;
    float v = g_z[head_ids[b] * HD + c] * w_rel[rel_ids[b] * HD + c];
    __nv_bfloat16 hi = __float2bfloat16(v);
    g_hrhi[idx] = hi;
    g_hrlo[idx] = __float2bfloat16(v - __bfloat162float(hi));
}

// ---------------- decoder via mma.sync bf16 (split-bf16, K-chunked, 2 CTAs/SM) -------
#define TROW 144
#define TILE_SB (128 * TROW)              // 18432 B per tile
#define DEC_SMEM (4 * TILE_SB)            // 73728 B

__global__ __launch_bounds__(256, 2) void decoder_mma_kernel(float* __restrict__ out) {
    extern __shared__ char smem[];
    char* sAhi = smem;
    char* sAlo = smem + TILE_SB;
    char* sBhi = smem + 2 * TILE_SB;
    char* sBlo = smem + 3 * TILE_SB;
    int tid = threadIdx.x;
    int wid = tid >> 5, lane = tid & 31;
    int col0 = blockIdx.x * 128;
    int row0 = blockIdx.y * 128;

    int wr = wid & 1, wc = wid >> 1;
    float acc[4][4][4];
#pragma unroll
    for (int mi = 0; mi < 4; mi++)
#pragma unroll
        for (int ni = 0; ni < 4; ni++)
#pragma unroll
            for (int x = 0; x < 4; x++) acc[mi][ni][x] = 0.f;

    int aRow = wr * 64 + (lane & 7) + ((lane >> 3) & 1) * 8;
    int aKoff = ((lane >> 4) & 1) * 16;
    uint32_t aBaseHi = smem_to_u32(sAhi) + aRow * TROW + aKoff;
    uint32_t aBaseLo = smem_to_u32(sAlo) + aRow * TROW + aKoff;
    int bRow = wc * 32 + (lane & 7);
    int bKoff = ((lane >> 3) & 1) * 16;
    uint32_t bBaseHi = smem_to_u32(sBhi) + bRow * TROW + bKoff;
    uint32_t bBaseLo = smem_to_u32(sBlo) + bRow * TROW + bKoff;

    const __nv_bfloat16* srcs[4] = {g_hrhi, g_hrlo, g_zhi, g_zlo};
    char* dsts[4] = {sAhi, sAlo, sBhi, sBlo};

#pragma unroll 1
    for (int kc = 0; kc < 2; kc++) {
#pragma unroll
        for (int t = 0; t < 4; t++) {
            bool isB = (t >= 2);
            const __nv_bfloat16* src = srcs[t];
            char* dst = dsts[t];
#pragma unroll
            for (int it = 0; it < 4; it++) {
                int idx = tid + it * 256;
                int r = idx >> 3, q = idx & 7;
                uint4 v = make_uint4(0u, 0u, 0u, 0u);
                int grow = (isB ? col0 : row0) + r;
                if (!isB || grow < NN)
                    v = *(const uint4*)(src + grow * HD + kc * 64 + q * 8);
                *(uint4*)(dst + r * TROW + q * 16) = v;
            }
        }
        __syncthreads();

#pragma unroll
        for (int ks = 0; ks < 4; ks++) {
            int ko = ks * 32;
            uint32_t bh[4][2], bl[4][2];
#pragma unroll
            for (int ni = 0; ni < 4; ni++) {
                ldm_x2(bh[ni][0], bh[ni][1], bBaseHi + ni * 8 * TROW + ko);
                ldm_x2(bl[ni][0], bl[ni][1], bBaseLo + ni * 8 * TROW + ko);
            }
#pragma unroll
            for (int mi = 0; mi < 4; mi++) {
                uint32_t ah0, ah1, ah2, ah3, al0, al1, al2, al3;
                ldm_x4(ah0, ah1, ah2, ah3, aBaseHi + mi * 16 * TROW + ko);
                ldm_x4(al0, al1, al2, al3, aBaseLo + mi * 16 * TROW + ko);
#pragma unroll
                for (int ni = 0; ni < 4; ni++) {
                    mma_bf16(acc[mi][ni], ah0, ah1, ah2, ah3, bh[ni][0], bh[ni][1]);
                    mma_bf16(acc[mi][ni], ah0, ah1, ah2, ah3, bl[ni][0], bl[ni][1]);
                    mma_bf16(acc[mi][ni], al0, al1, al2, al3, bh[ni][0], bh[ni][1]);
                }
            }
        }
        __syncthreads();
    }

#pragma unroll
    for (int mi = 0; mi < 4; mi++) {
        int rgA = row0 + wr * 64 + mi * 16 + (lane >> 2);
        float* orow0 = out + (size_t)rgA * NN;
        float* orow1 = out + (size_t)(rgA + 8) * NN;
#pragma unroll
        for (int ni = 0; ni < 4; ni++) {
            int cg = col0 + wc * 32 + ni * 8 + (lane & 3) * 2;
            if (cg < NN) {
                *(float2*)(orow0 + cg) = make_float2(acc[mi][ni][0], acc[mi][ni][1]);
                *(float2*)(orow1 + cg) = make_float2(acc[mi][ni][2], acc[mi][ni][3]);
            }
        }
    }
}

// ---------------- launch: capture-forked streams ----------------
extern "C" void kernel_launch(void* const* d_in, const int* in_sizes, int n_in,
                              void* d_out, int out_size) {
    const int*   h        = (const int*)d_in[0];
    const int*   src      = (const int*)d_in[1];
    const int*   dst      = (const int*)d_in[2];
    const int*   etypes   = (const int*)d_in[3];
    const float* norm     = (const float*)d_in[4];
    const int*   head_ids = (const int*)d_in[5];
    const int*   rel_ids  = (const int*)d_in[6];
    const float* embed    = (const float*)d_in[7];
    const float* W1       = (const float*)d_in[8];
    const float* lw1      = (const float*)d_in[9];
    const float* b1       = (const float*)d_in[10];
    const float* W2       = (const float*)d_in[11];
    const float* lw2      = (const float*)d_in[12];
    const float* b2       = (const float*)d_in[13];
    const float* w_rel    = (const float*)d_in[14];
    const float* eps      = (const float*)d_in[15];
    float* out = (float*)d_out;

    static cudaStream_t s1 = nullptr, s2 = nullptr;
    static cudaEvent_t eFork, eSort, eEpi1, eG2;
    if (!s1) {
        cudaStreamCreateWithFlags(&s1, cudaStreamNonBlocking);
        cudaStreamCreateWithFlags(&s2, cudaStreamNonBlocking);
        cudaEventCreateWithFlags(&eFork, cudaEventDisableTiming);
        cudaEventCreateWithFlags(&eSort, cudaEventDisableTiming);
        cudaEventCreateWithFlags(&eEpi1, cudaEventDisableTiming);
        cudaEventCreateWithFlags(&eG2, cudaEventDisableTiming);
        cudaFuncSetAttribute(decoder_mma_kernel,
                             cudaFuncAttributeMaxDynamicSharedMemorySize, DEC_SMEM);
        cudaFuncSetAttribute(edge2_kernel,
                             cudaFuncAttributeMaxDynamicSharedMemorySize,
                             E2_W2FLOATS * 4);
    }

    // fork: dst-CSR sort on s1; sl1gemm on main — independent
    cudaEventRecord(eFork, 0);
    cudaStreamWaitEvent(s1, eFork, 0);

    hist_kernel<<<EE / 256, 256, 0, s1>>>(dst);
    scan_kernel<<<1, 1024, 0, s1>>>();
    scatter_kernel<<<EE / 256, 256, 0, s1>>>(src, dst, etypes, norm, h);
    cudaEventRecord(eSort, s1);

    sl1gemm_kernel<<<NN / 32, 256>>>(lw1, b1, h, embed);   // main, overlaps sort

    // edge1 on main (needs CSR)
    cudaStreamWaitEvent(0, eSort, 0);
    edge1_kernel<<<NN / 8, 256>>>(W1, embed);

    // epilogue 1 (sl1gemm already done on same stream)
    sl1epi_kernel<<<(NN * HD / 4) / 256, 256>>>();
    cudaEventRecord(eEpi1, 0);

    // sl2 GEMM on s2, edge2 on main (both read out1)
    cudaStreamWaitEvent(s2, eEpi1, 0);
    sl2gemm_kernel<<<NN / 32, 256, 0, s2>>>(lw2, b2);
    cudaEventRecord(eG2, s2);

    edge2_kernel<<<E2_BLOCKS, E2_THREADS, E2_W2FLOATS * 4>>>(W2);

    // join, epilogue 2 + tail
    cudaStreamWaitEvent(0, eG2, 0);
    sl2epi_kernel<<<(NN * 32) / 256, 256>>>(eps);
    hr_kernel<<<(2048 * HD) / 256, 256>>>(head_ids, rel_ids, w_rel);
    dim3 dgrid((NN + 127) / 128, 2048 / 128);
    decoder_mma_kernel<<<dgrid, 256, DEC_SMEM>>>(out);
}

// round 16
// speedup vs baseline: 1.6388x; 1.6388x over previous
#include <cuda_runtime.h>
#include <cuda_bf16.h>
#include <cstdint>

#define NN 20000
#define EE 256000
#define HD 128
#define NRR 100
#define EPW 8    // edges per warp-run in rel-sorted edge2

// ---------------- scratch (static device globals; no allocation) ----------------
__device__ float g_agg1[NN * HD];      // layer1 aggregation (plain stores via CSR)
__device__ float g_tmp1[NN * HD];      // x0 @ lw1 + b1
__device__ float g_out1[NN * HD];      // layer1 output (relu)
__device__ float g_agg2[NN * 2 * HD];  // layer2 aggregation (atomics)
__device__ float g_tmp2[NN * 2 * HD];  // out1 @ lw2 + b2
__device__ float g_z[NN * HD];         // sampled latent (fp32, for hr gather)
__device__ __nv_bfloat16 g_zhi[NN * HD];
__device__ __nv_bfloat16 g_zlo[NN * HD];
__device__ __nv_bfloat16 g_hrhi[2048 * HD];
__device__ __nv_bfloat16 g_hrlo[2048 * HD];
// rel-sort state (edge2)
__device__ int   g_hist[NRR + 1];      // zero at load; re-zeroed by scan each run
__device__ int   g_cursor[NRR];
__device__ int4  g_recs[EE];           // rel-sorted {src, dst, rel, norm}
// dst-CSR state (edge1)
__device__ int   g_cnt[NN];            // zero at load; re-zeroed by scand each run
__device__ int   g_off[NN + 1];
__device__ int   g_cur[NN];
__device__ int4  g_recsd[EE];          // dst-sorted {hsrc, rel, norm, pad}

// ---------------- helpers ----------------
__device__ __forceinline__ unsigned long long pk2(float x, float y) {
    unsigned long long r;
    asm("mov.b64 %0, {%1, %2};" : "=l"(r) : "f"(x), "f"(y));
    return r;
}
__device__ __forceinline__ void upk2(unsigned long long p, float& x, float& y) {
    asm("mov.b64 {%0, %1}, %2;" : "=f"(x), "=f"(y) : "l"(p));
}
__device__ __forceinline__ void fma2(unsigned long long& d, unsigned long long a, unsigned long long b) {
    asm("fma.rn.f32x2 %0, %1, %2, %0;" : "+l"(d) : "l"(a), "l"(b));
}
__device__ __forceinline__ void red_add_v4(float* addr, float a, float b, float c, float d) {
    asm volatile("red.global.add.v4.f32 [%0], {%1, %2, %3, %4};"
                 :: "l"(addr), "f"(a), "f"(b), "f"(c), "f"(d));
}
__device__ __forceinline__ float softplus_f(float x) {
    return fmaxf(x, 0.f) + log1pf(expf(-fabsf(x)));
}
__device__ __forceinline__ uint32_t smem_to_u32(const void* p) {
    uint32_t a;
    asm("{ .reg .u64 t; cvta.to.shared.u64 t, %1; cvt.u32.u64 %0, t; }" : "=r"(a) : "l"(p));
    return a;
}
__device__ __forceinline__ void ldm_x4(uint32_t& r0, uint32_t& r1, uint32_t& r2, uint32_t& r3,
                                       uint32_t addr) {
    asm volatile("ldmatrix.sync.aligned.m8n8.x4.shared.b16 {%0,%1,%2,%3}, [%4];"
                 : "=r"(r0), "=r"(r1), "=r"(r2), "=r"(r3) : "r"(addr));
}
__device__ __forceinline__ void ldm_x2(uint32_t& r0, uint32_t& r1, uint32_t addr) {
    asm volatile("ldmatrix.sync.aligned.m8n8.x2.shared.b16 {%0,%1}, [%2];"
                 : "=r"(r0), "=r"(r1) : "r"(addr));
}
__device__ __forceinline__ void mma_bf16(float* c, uint32_t a0, uint32_t a1, uint32_t a2,
                                         uint32_t a3, uint32_t b0, uint32_t b1) {
    asm volatile(
        "mma.sync.aligned.m16n8k16.row.col.f32.bf16.bf16.f32 "
        "{%0,%1,%2,%3}, {%4,%5,%6,%7}, {%8,%9}, {%0,%1,%2,%3};"
        : "+f"(c[0]), "+f"(c[1]), "+f"(c[2]), "+f"(c[3])
        : "r"(a0), "r"(a1), "r"(a2), "r"(a3), "r"(b0), "r"(b1));
}

// ---------------- zero kernel for agg2 (edge2 still uses atomics) ----------------
__global__ __launch_bounds__(256) void zero2_kernel() {
    int idx = blockIdx.x * 256 + threadIdx.x;
    ((float4*)g_agg2)[idx] = make_float4(0.f, 0.f, 0.f, 0.f);
}

// ================= rel-sort chain (for edge2) =================
__global__ __launch_bounds__(256) void hist_kernel(const int* __restrict__ et) {
    __shared__ int sh[NRR];
    int tid = threadIdx.x;
    if (tid < NRR) sh[tid] = 0;
    __syncthreads();
    int e0 = blockIdx.x * 1024 + tid;
#pragma unroll
    for (int j = 0; j < 4; j++) atomicAdd(&sh[et[e0 + j * 256]], 1);
    __syncthreads();
    if (tid < NRR && sh[tid]) atomicAdd(&g_hist[tid + 1], sh[tid]);
}

__global__ __launch_bounds__(128) void scan_kernel() {
    __shared__ int s[128];
    int tid = threadIdx.x;
    int v0 = (tid <= NRR) ? g_hist[tid] : 0;
    s[tid] = v0;
    __syncthreads();
#pragma unroll
    for (int d = 1; d < 128; d <<= 1) {
        int v = (tid >= d) ? s[tid - d] : 0;
        __syncthreads();
        s[tid] += v;
        __syncthreads();
    }
    if (tid < NRR) g_cursor[tid] = s[tid];
    if (tid <= NRR) g_hist[tid] = 0;   // ready for next run
}

__global__ __launch_bounds__(256) void scatter_kernel(const int* __restrict__ src,
                                                      const int* __restrict__ dst,
                                                      const int* __restrict__ et,
                                                      const float* __restrict__ norm) {
    __shared__ int cnt[NRR];
    __shared__ int base[NRR];
    int tid = threadIdx.x;
    if (tid < NRR) cnt[tid] = 0;
    __syncthreads();
    int e0 = blockIdx.x * 1024 + tid;
    int r[4], s[4], d[4], nm[4];
#pragma unroll
    for (int j = 0; j < 4; j++) {
        int e = e0 + j * 256;
        r[j] = et[e]; s[j] = src[e]; d[j] = dst[e]; nm[j] = __float_as_int(norm[e]);
        atomicAdd(&cnt[r[j]], 1);
    }
    __syncthreads();
    if (tid < NRR) {
        int c = cnt[tid];
        base[tid] = c ? atomicAdd(&g_cursor[tid], c) : 0;
        cnt[tid] = 0;
    }
    __syncthreads();
#pragma unroll
    for (int j = 0; j < 4; j++) {
        int pos = base[r[j]] + atomicAdd(&cnt[r[j]], 1);
        g_recs[pos] = make_int4(s[j], d[j], r[j], nm[j]);
    }
}

// ================= dst-CSR chain (for edge1) =================
__global__ __launch_bounds__(256) void histd_kernel(const int* __restrict__ dst) {
    int e = blockIdx.x * 256 + threadIdx.x;
    atomicAdd(&g_cnt[dst[e]], 1);
}

__global__ __launch_bounds__(1024) void scand_kernel() {
    __shared__ int part[1024];
    int t = threadIdx.x;
    int base = t * 20;
    int loc[20];
    int sum = 0;
#pragma unroll
    for (int k = 0; k < 20; k++) {
        int i = base + k;
        int c = (i < NN) ? g_cnt[i] : 0;
        loc[k] = sum;
        sum += c;
    }
    part[t] = sum;
    __syncthreads();
#pragma unroll
    for (int d = 1; d < 1024; d <<= 1) {
        int v = (t >= d) ? part[t - d] : 0;
        __syncthreads();
        part[t] += v;
        __syncthreads();
    }
    int pref = t ? part[t - 1] : 0;
#pragma unroll
    for (int k = 0; k < 20; k++) {
        int i = base + k;
        if (i < NN) {
            int o = pref + loc[k];
            g_off[i] = o;
            g_cur[i] = o;
            g_cnt[i] = 0;   // ready for next replay
        }
    }
    if (t == 1023) g_off[NN] = part[1023];
}

__global__ __launch_bounds__(256) void scatterd_kernel(const int* __restrict__ src,
                                                       const int* __restrict__ dst,
                                                       const int* __restrict__ et,
                                                       const float* __restrict__ norm,
                                                       const int* __restrict__ h) {
    int e = blockIdx.x * 256 + threadIdx.x;
    int s = src[e];
    int d = dst[e];
    int pos = atomicAdd(&g_cur[d], 1);
    g_recsd[pos] = make_int4(h[s], et[e], __float_as_int(norm[e]), 0);
}

// ---------------- layer1 edges: warp per dst, register accumulation, NO atomics --------
// lane l owns bdd blocks 2l,2l+1 -> out cols 4l..4l+3. W1 (100KB) L1-hot via __ldg;
// x + recs bypass L1 via __ldcg. (Measured 33.6us in R9.)
__global__ __launch_bounds__(256) void edge1_kernel(const float* __restrict__ W1,
                                                    const float* __restrict__ embed) {
    int d = (blockIdx.x * 256 + threadIdx.x) >> 5;   // 0..19999 exact
    int lane = threadIdx.x & 31;
    int s0 = __ldg(&g_off[d]), s1 = __ldg(&g_off[d + 1]);
    float a0 = 0.f, a1 = 0.f, a2 = 0.f, a3 = 0.f;
    if (s0 < s1) {
        int4 rec = __ldcg(&g_recsd[s0]);
#pragma unroll 1
        for (int i = s0; i < s1; i++) {
            int4 nrec = (i + 1 < s1) ? __ldcg(&g_recsd[i + 1]) : rec;
            float4 xv = __ldcg((const float4*)(embed + rec.x * HD) + lane);
            const float4* w4 = (const float4*)(W1 + rec.y * 256 + lane * 8);
            float4 wa = __ldg(w4), wb = __ldg(w4 + 1);
            float nrm = __int_as_float(rec.z);
            a0 += (xv.x * wa.x + xv.y * wa.z) * nrm;
            a1 += (xv.x * wa.y + xv.y * wa.w) * nrm;
            a2 += (xv.z * wb.x + xv.w * wb.z) * nrm;
            a3 += (xv.z * wb.y + xv.w * wb.w) * nrm;
            rec = nrec;
        }
    }
    ((float4*)(g_agg1 + d * HD))[lane] = make_float4(a0, a1, a2, a3);
}

// ---------------- sl1 GEMM: tmp1 = embed[h] @ lw1 + b1 (overlaps sorts) ----------------
__global__ __launch_bounds__(256) void sl1gemm_kernel(const float* __restrict__ lw1,
                                                      const float* __restrict__ b1,
                                                      const int* __restrict__ h,
                                                      const float* __restrict__ embed) {
    __shared__ float4 ws4[32][32];
    __shared__ float xsh[8][4][33];
    int tid = threadIdx.x;
    int w = tid >> 5, lane = tid & 31;
    int row0 = blockIdx.x * 32 + w * 4;
    int hr_[4];
#pragma unroll
    for (int j = 0; j < 4; j++) hr_[j] = __ldg(&h[row0 + j]);
    unsigned long long acc[4][2];
#pragma unroll
    for (int j = 0; j < 4; j++) { acc[j][0] = 0ULL; acc[j][1] = 0ULL; }
    const float4* lw4 = (const float4*)lw1;
    for (int kc = 0; kc < 4; kc++) {
#pragma unroll
        for (int it = 0; it < 4; it++) {
            int idx = tid + it * 256;
            int k = idx >> 5, c = idx & 31;
            ws4[k][c] = lw4[(kc * 32 + k) * 32 + c];
        }
#pragma unroll
        for (int j = 0; j < 4; j++)
            xsh[w][j][lane] = embed[hr_[j] * HD + kc * 32 + lane];
        __syncthreads();
#pragma unroll
        for (int k = 0; k < 32; k++) {
            float4 wv = ws4[k][lane];
            unsigned long long wlo = pk2(wv.x, wv.y), whi = pk2(wv.z, wv.w);
#pragma unroll
            for (int j = 0; j < 4; j++) {
                float xv = xsh[w][j][k];
                unsigned long long x2 = pk2(xv, xv);
                fma2(acc[j][0], x2, wlo);
                fma2(acc[j][1], x2, whi);
            }
        }
        __syncthreads();
    }
    float4 bv = ((const float4*)b1)[lane];
#pragma unroll
    for (int j = 0; j < 4; j++) {
        float o0, o1, o2, o3;
        upk2(acc[j][0], o0, o1);
        upk2(acc[j][1], o2, o3);
        ((float4*)(g_tmp1 + (row0 + j) * HD))[lane] =
            make_float4(o0 + bv.x, o1 + bv.y, o2 + bv.z, o3 + bv.w);
    }
}

// ---------------- sl1 epilogue: out1 = relu(agg1 + tmp1) ----------------
__global__ __launch_bounds__(256) void sl1epi_kernel() {
    int idx = blockIdx.x * 256 + threadIdx.x;   // float4 index
    float4 a = ((const float4*)g_agg1)[idx];
    float4 t = ((const float4*)g_tmp1)[idx];
    ((float4*)g_out1)[idx] = make_float4(fmaxf(a.x + t.x, 0.f), fmaxf(a.y + t.y, 0.f),
                                         fmaxf(a.z + t.z, 0.f), fmaxf(a.w + t.w, 0.f));
}

// ---------------- layer2 edges: 2 warps per EPW-run (half the 256 cols each) ------------
// R13-validated. half hf, lane l -> bdd block b = hf*32+l.
__global__ __launch_bounds__(256) void edge2_kernel(const float* __restrict__ W2) {
    int gw = (blockIdx.x * 256 + threadIdx.x) >> 5;
    int lane = threadIdx.x & 31;
    int run = gw >> 1, hf = gw & 1;
    int e0 = run * EPW;
    int b = hf * 32 + lane;
    int cur = -1;
    float4 wA, wB;   // W2[r][b][0][0..3], W2[r][b][1][0..3]
    int4 r0 = __ldg(&g_recs[e0]);
    int4 r1 = __ldg(&g_recs[e0 + 1]);
#pragma unroll 1
    for (int e = 0; e < EPW; e += 2) {
        int4 n0 = r0, n1 = r1;
        if (e + 2 < EPW) {
            n0 = __ldg(&g_recs[e0 + e + 2]);
            n1 = __ldg(&g_recs[e0 + e + 3]);
        }
        float2 xv0 = ((const float2*)(g_out1 + r0.x * HD))[b];
        float2 xv1 = ((const float2*)(g_out1 + r1.x * HD))[b];
        float nrm0 = __int_as_float(r0.w), nrm1 = __int_as_float(r1.w);
        if (r0.z != cur) {
            const float4* w4 = (const float4*)(W2 + r0.z * 512 + b * 8);
            wA = __ldg(w4); wB = __ldg(w4 + 1);
            cur = r0.z;
        }
        {
            float o0 = (xv0.x * wA.x + xv0.y * wB.x) * nrm0;
            float o1 = (xv0.x * wA.y + xv0.y * wB.y) * nrm0;
            float o2 = (xv0.x * wA.z + xv0.y * wB.z) * nrm0;
            float o3 = (xv0.x * wA.w + xv0.y * wB.w) * nrm0;
            red_add_v4(g_agg2 + r0.y * 2 * HD + b * 4, o0, o1, o2, o3);
        }
        if (r1.z != cur) {
            const float4* w4 = (const float4*)(W2 + r1.z * 512 + b * 8);
            wA = __ldg(w4); wB = __ldg(w4 + 1);
            cur = r1.z;
        }
        {
            float o0 = (xv1.x * wA.x + xv1.y * wB.x) * nrm1;
            float o1 = (xv1.x * wA.y + xv1.y * wB.y) * nrm1;
            float o2 = (xv1.x * wA.z + xv1.y * wB.z) * nrm1;
            float o3 = (xv1.x * wA.w + xv1.y * wB.w) * nrm1;
            red_add_v4(g_agg2 + r1.y * 2 * HD + b * 4, o0, o1, o2, o3);
        }
        r0 = n0; r1 = n1;
    }
}

// ---------------- sl2 GEMM: tmp2 = out1 @ lw2 + b2 (overlaps edge2) ----------------
__global__ __launch_bounds__(256) void sl2gemm_kernel(const float* __restrict__ lw2,
                                                      const float* __restrict__ b2) {
    __shared__ float4 ws4[32][64];
    __shared__ float xsh[8][4][33];
    int tid = threadIdx.x;
    int w = tid >> 5, lane = tid & 31;
    int row0 = blockIdx.x * 32 + w * 4;
    unsigned long long acc[4][4];
#pragma unroll
    for (int j = 0; j < 4; j++)
#pragma unroll
        for (int g = 0; g < 4; g++) acc[j][g] = 0ULL;
    const float4* lw4 = (const float4*)lw2;
    for (int kc = 0; kc < 4; kc++) {
#pragma unroll
        for (int it = 0; it < 8; it++) {
            int idx = tid + it * 256;
            int k = idx >> 6, c = idx & 63;
            ws4[k][c] = lw4[(kc * 32 + k) * 64 + c];
        }
#pragma unroll
        for (int j = 0; j < 4; j++)
            xsh[w][j][lane] = g_out1[(row0 + j) * HD + kc * 32 + lane];
        __syncthreads();
#pragma unroll
        for (int k = 0; k < 32; k++) {
            float4 w0 = ws4[k][lane];
            float4 w1 = ws4[k][32 + lane];
            unsigned long long wl0 = pk2(w0.x, w0.y), wh0 = pk2(w0.z, w0.w);
            unsigned long long wl1 = pk2(w1.x, w1.y), wh1 = pk2(w1.z, w1.w);
#pragma unroll
            for (int j = 0; j < 4; j++) {
                float xv = xsh[w][j][k];
                unsigned long long x2 = pk2(xv, xv);
                fma2(acc[j][0], x2, wl0);
                fma2(acc[j][1], x2, wh0);
                fma2(acc[j][2], x2, wl1);
                fma2(acc[j][3], x2, wh1);
            }
        }
        __syncthreads();
    }
    float4 b0 = ((const float4*)b2)[lane];
    float4 b1v = ((const float4*)b2)[32 + lane];
#pragma unroll
    for (int j = 0; j < 4; j++) {
        int row = row0 + j;
        float m0, m1, m2, m3, v0, v1, v2, v3;
        upk2(acc[j][0], m0, m1);
        upk2(acc[j][1], m2, m3);
        upk2(acc[j][2], v0, v1);
        upk2(acc[j][3], v2, v3);
        ((float4*)(g_tmp2 + row * 2 * HD))[lane] =
            make_float4(m0 + b0.x, m1 + b0.y, m2 + b0.z, m3 + b0.w);
        ((float4*)(g_tmp2 + row * 2 * HD))[32 + lane] =
            make_float4(v0 + b1v.x, v1 + b1v.y, v2 + b1v.z, v3 + b1v.w);
    }
}

// ---------------- sl2 epilogue: z = m + sqrt(softplus(v)+1e-8)*eps, + bf16 split --------
__global__ __launch_bounds__(256) void sl2epi_kernel(const float* __restrict__ eps) {
    int gid = blockIdx.x * 256 + threadIdx.x;   // 0 .. NN*32-1
    int row = gid >> 5, lane = gid & 31;
    float4 m = ((const float4*)(g_tmp2 + row * 2 * HD))[lane];
    float4 hv = ((const float4*)(g_tmp2 + row * 2 * HD))[32 + lane];
    float4 am = ((const float4*)(g_agg2 + row * 2 * HD))[lane];
    float4 av = ((const float4*)(g_agg2 + row * 2 * HD))[32 + lane];
    float4 ev = ((const float4*)(eps + row * HD))[lane];
    float m0 = m.x + am.x, m1 = m.y + am.y, m2 = m.z + am.z, m3 = m.w + am.w;
    float v0 = hv.x + av.x, v1 = hv.y + av.y, v2 = hv.z + av.z, v3 = hv.w + av.w;
    float z0 = m0 + sqrtf(softplus_f(v0) + 1e-8f) * ev.x;
    float z1 = m1 + sqrtf(softplus_f(v1) + 1e-8f) * ev.y;
    float z2 = m2 + sqrtf(softplus_f(v2) + 1e-8f) * ev.z;
    float z3 = m3 + sqrtf(softplus_f(v3) + 1e-8f) * ev.w;
    ((float4*)(g_z + row * HD))[lane] = make_float4(z0, z1, z2, z3);
    __nv_bfloat16 h0b = __float2bfloat16(z0), h1b = __float2bfloat16(z1);
    __nv_bfloat16 h2b = __float2bfloat16(z2), h3b = __float2bfloat16(z3);
    __nv_bfloat16 l0b = __float2bfloat16(z0 - __bfloat162float(h0b));
    __nv_bfloat16 l1b = __float2bfloat16(z1 - __bfloat162float(h1b));
    __nv_bfloat16 l2b = __float2bfloat16(z2 - __bfloat162float(h2b));
    __nv_bfloat16 l3b = __float2bfloat16(z3 - __bfloat162float(h3b));
    __nv_bfloat162* zh = (__nv_bfloat162*)(g_zhi + row * HD);
    __nv_bfloat162* zl = (__nv_bfloat162*)(g_zlo + row * HD);
    zh[lane * 2]     = __nv_bfloat162(h0b, h1b);
    zh[lane * 2 + 1] = __nv_bfloat162(h2b, h3b);
    zl[lane * 2]     = __nv_bfloat162(l0b, l1b);
    zl[lane * 2 + 1] = __nv_bfloat162(l2b, l3b);
}

// ---------------- hr = z[head_ids] * w_rel[rel_ids], split to bf16 hi/lo ----------------
__global__ __launch_bounds__(256) void hr_kernel(const int* __restrict__ head_ids,
                                                 const int* __restrict__ rel_ids,
                                                 const float* __restrict__ w_rel) {
    int idx = blockIdx.x * blockDim.x + threadIdx.x;  // 0 .. 2048*128-1
    int b = idx >> 7, c = idx & 127;
    float v = g_z[head_ids[b] * HD + c] * w_rel[rel_ids[b] * HD + c];
    __nv_bfloat16 hi = __float2bfloat16(v);
    g_hrhi[idx] = hi;
    g_hrlo[idx] = __float2bfloat16(v - __bfloat162float(hi));
}

// ---------------- decoder via mma.sync bf16 (split-bf16, K-chunked, 2 CTAs/SM) -------
#define TROW 144
#define TILE_SB (128 * TROW)              // 18432 B per tile
#define DEC_SMEM (4 * TILE_SB)            // 73728 B

__global__ __launch_bounds__(256, 2) void decoder_mma_kernel(float* __restrict__ out) {
    extern __shared__ char smem[];
    char* sAhi = smem;
    char* sAlo = smem + TILE_SB;
    char* sBhi = smem + 2 * TILE_SB;
    char* sBlo = smem + 3 * TILE_SB;
    int tid = threadIdx.x;
    int wid = tid >> 5, lane = tid & 31;
    int col0 = blockIdx.x * 128;
    int row0 = blockIdx.y * 128;

    int wr = wid & 1, wc = wid >> 1;
    float acc[4][4][4];
#pragma unroll
    for (int mi = 0; mi < 4; mi++)
#pragma unroll
        for (int ni = 0; ni < 4; ni++)
#pragma unroll
            for (int x = 0; x < 4; x++) acc[mi][ni][x] = 0.f;

    int aRow = wr * 64 + (lane & 7) + ((lane >> 3) & 1) * 8;
    int aKoff = ((lane >> 4) & 1) * 16;
    uint32_t aBaseHi = smem_to_u32(sAhi) + aRow * TROW + aKoff;
    uint32_t aBaseLo = smem_to_u32(sAlo) + aRow * TROW + aKoff;
    int bRow = wc * 32 + (lane & 7);
    int bKoff = ((lane >> 3) & 1) * 16;
    uint32_t bBaseHi = smem_to_u32(sBhi) + bRow * TROW + bKoff;
    uint32_t bBaseLo = smem_to_u32(sBlo) + bRow * TROW + bKoff;

    const __nv_bfloat16* srcs[4] = {g_hrhi, g_hrlo, g_zhi, g_zlo};
    char* dsts[4] = {sAhi, sAlo, sBhi, sBlo};

#pragma unroll 1
    for (int kc = 0; kc < 2; kc++) {
#pragma unroll
        for (int t = 0; t < 4; t++) {
            bool isB = (t >= 2);
            const __nv_bfloat16* src = srcs[t];
            char* dst = dsts[t];
#pragma unroll
            for (int it = 0; it < 4; it++) {
                int idx = tid + it * 256;
                int r = idx >> 3, q = idx & 7;
                uint4 v = make_uint4(0u, 0u, 0u, 0u);
                int grow = (isB ? col0 : row0) + r;
                if (!isB || grow < NN)
                    v = *(const uint4*)(src + grow * HD + kc * 64 + q * 8);
                *(uint4*)(dst + r * TROW + q * 16) = v;
            }
        }
        __syncthreads();

#pragma unroll
        for (int ks = 0; ks < 4; ks++) {
            int ko = ks * 32;
            uint32_t bh[4][2], bl[4][2];
#pragma unroll
            for (int ni = 0; ni < 4; ni++) {
                ldm_x2(bh[ni][0], bh[ni][1], bBaseHi + ni * 8 * TROW + ko);
                ldm_x2(bl[ni][0], bl[ni][1], bBaseLo + ni * 8 * TROW + ko);
            }
#pragma unroll
            for (int mi = 0; mi < 4; mi++) {
                uint32_t ah0, ah1, ah2, ah3, al0, al1, al2, al3;
                ldm_x4(ah0, ah1, ah2, ah3, aBaseHi + mi * 16 * TROW + ko);
                ldm_x4(al0, al1, al2, al3, aBaseLo + mi * 16 * TROW + ko);
#pragma unroll
                for (int ni = 0; ni < 4; ni++) {
                    mma_bf16(acc[mi][ni], ah0, ah1, ah2, ah3, bh[ni][0], bh[ni][1]);
                    mma_bf16(acc[mi][ni], ah0, ah1, ah2, ah3, bl[ni][0], bl[ni][1]);
                    mma_bf16(acc[mi][ni], al0, al1, al2, al3, bh[ni][0], bh[ni][1]);
                }
            }
        }
        __syncthreads();
    }

#pragma unroll
    for (int mi = 0; mi < 4; mi++) {
        int rgA = row0 + wr * 64 + mi * 16 + (lane >> 2);
        float* orow0 = out + (size_t)rgA * NN;
        float* orow1 = out + (size_t)(rgA + 8) * NN;
#pragma unroll
        for (int ni = 0; ni < 4; ni++) {
            int cg = col0 + wc * 32 + ni * 8 + (lane & 3) * 2;
            if (cg < NN) {
                *(float2*)(orow0 + cg) = make_float2(acc[mi][ni][0], acc[mi][ni][1]);
                *(float2*)(orow1 + cg) = make_float2(acc[mi][ni][2], acc[mi][ni][3]);
            }
        }
    }
}

// ---------------- launch: capture-forked streams ----------------
extern "C" void kernel_launch(void* const* d_in, const int* in_sizes, int n_in,
                              void* d_out, int out_size) {
    const int*   h        = (const int*)d_in[0];
    const int*   src      = (const int*)d_in[1];
    const int*   dst      = (const int*)d_in[2];
    const int*   etypes   = (const int*)d_in[3];
    const float* norm     = (const float*)d_in[4];
    const int*   head_ids = (const int*)d_in[5];
    const int*   rel_ids  = (const int*)d_in[6];
    const float* embed    = (const float*)d_in[7];
    const float* W1       = (const float*)d_in[8];
    const float* lw1      = (const float*)d_in[9];
    const float* b1       = (const float*)d_in[10];
    const float* W2       = (const float*)d_in[11];
    const float* lw2      = (const float*)d_in[12];
    const float* b2       = (const float*)d_in[13];
    const float* w_rel    = (const float*)d_in[14];
    const float* eps      = (const float*)d_in[15];
    float* out = (float*)d_out;

    static cudaStream_t s1 = nullptr, s2 = nullptr;
    static cudaEvent_t eFork, eRel, eDst, eEpi1, eG2;
    if (!s1) {
        cudaStreamCreateWithFlags(&s1, cudaStreamNonBlocking);
        cudaStreamCreateWithFlags(&s2, cudaStreamNonBlocking);
        cudaEventCreateWithFlags(&eFork, cudaEventDisableTiming);
        cudaEventCreateWithFlags(&eRel, cudaEventDisableTiming);
        cudaEventCreateWithFlags(&eDst, cudaEventDisableTiming);
        cudaEventCreateWithFlags(&eEpi1, cudaEventDisableTiming);
        cudaEventCreateWithFlags(&eG2, cudaEventDisableTiming);
        cudaFuncSetAttribute(decoder_mma_kernel,
                             cudaFuncAttributeMaxDynamicSharedMemorySize, DEC_SMEM);
    }

    // fork: rel-sort + zero2 on s1 (edge2 deps), dst-CSR sort on s2 (edge1 deps),
    // sl1gemm on main — all independent
    cudaEventRecord(eFork, 0);
    cudaStreamWaitEvent(s1, eFork, 0);
    cudaStreamWaitEvent(s2, eFork, 0);

    hist_kernel<<<EE / 1024, 256, 0, s1>>>(etypes);
    scan_kernel<<<1, 128, 0, s1>>>();
    scatter_kernel<<<EE / 1024, 256, 0, s1>>>(src, dst, etypes, norm);
    zero2_kernel<<<(NN * 2 * HD / 4) / 256, 256, 0, s1>>>();
    cudaEventRecord(eRel, s1);

    histd_kernel<<<EE / 256, 256, 0, s2>>>(dst);
    scand_kernel<<<1, 1024, 0, s2>>>();
    scatterd_kernel<<<EE / 256, 256, 0, s2>>>(src, dst, etypes, norm, h);
    cudaEventRecord(eDst, s2);

    sl1gemm_kernel<<<NN / 32, 256>>>(lw1, b1, h, embed);   // main, overlaps sorts

    // edge1 on main (needs dst-CSR)
    cudaStreamWaitEvent(0, eDst, 0);
    edge1_kernel<<<NN / 8, 256>>>(W1, embed);

    // epilogue 1 (sl1gemm already done on same stream)
    sl1epi_kernel<<<(NN * HD / 4) / 256, 256>>>();
    cudaEventRecord(eEpi1, 0);

    // sl2 GEMM on s2, edge2 on main (both read out1)
    cudaStreamWaitEvent(s2, eEpi1, 0);
    sl2gemm_kernel<<<NN / 32, 256, 0, s2>>>(lw2, b2);
    cudaEventRecord(eG2, s2);

    cudaStreamWaitEvent(0, eRel, 0);
    edge2_kernel<<<(EE * 2) / (EPW * 8), 256>>>(W2);

    // join, epilogue 2 + tail
    cudaStreamWaitEvent(0, eG2, 0);
    sl2epi_kernel<<<(NN * 32) / 256, 256>>>(eps);
    hr_kernel<<<(2048 * HD) / 256, 256>>>(head_ids, rel_ids, w_rel);
    dim3 dgrid((NN + 127) / 128, 2048 / 128);
    decoder_mma_kernel<<<dgrid, 256, DEC_SMEM>>>(out);
}

// round 17
// speedup vs baseline: 1.8581x; 1.1338x over previous
#include <cuda_runtime.h>
#include <cuda_bf16.h>
#include <cstdint>

#define NN 20000
#define EE 256000
#define HD 128
#define NRR 100
#define EPW 4    // edges per warp-run in sorted edge kernels

// ---------------- scratch (static device globals; no allocation) ----------------
__device__ float g_agg1[NN * HD];      // layer1 aggregation (atomics)
__device__ float g_tmp1[NN * HD];      // x0 @ lw1 + b1
__device__ float g_out1[NN * HD];      // layer1 output (relu)
__device__ float g_agg2[NN * 2 * HD];  // layer2 aggregation (atomics)
__device__ float g_tmp2[NN * 2 * HD];  // out1 @ lw2 + b2
__device__ float g_z[NN * HD];         // sampled latent (fp32, for hr gather)
__device__ __nv_bfloat16 g_zhi[NN * HD];
__device__ __nv_bfloat16 g_zlo[NN * HD];
__device__ __nv_bfloat16 g_hrhi[2048 * HD];
__device__ __nv_bfloat16 g_hrlo[2048 * HD];
__device__ int   g_hist[NRR + 1];      // zero at load; re-zeroed by scan each run
__device__ int   g_cursor[NRR];        // scatter cursors
__device__ int4  g_recs[EE];           // rel-sorted edge records {src, dst, rel, norm}
__device__ int   g_hsrc[EE];           // h[src] per sorted edge

// ---------------- helpers ----------------
__device__ __forceinline__ unsigned long long pk2(float x, float y) {
    unsigned long long r;
    asm("mov.b64 %0, {%1, %2};" : "=l"(r) : "f"(x), "f"(y));
    return r;
}
__device__ __forceinline__ void upk2(unsigned long long p, float& x, float& y) {
    asm("mov.b64 {%0, %1}, %2;" : "=f"(x), "=f"(y) : "l"(p));
}
__device__ __forceinline__ void fma2(unsigned long long& d, unsigned long long a, unsigned long long b) {
    asm("fma.rn.f32x2 %0, %1, %2, %0;" : "+l"(d) : "l"(a), "l"(b));
}
__device__ __forceinline__ void red_add_v4(float* addr, float a, float b, float c, float d) {
    asm volatile("red.global.add.v4.f32 [%0], {%1, %2, %3, %4};"
                 :: "l"(addr), "f"(a), "f"(b), "f"(c), "f"(d));
}
__device__ __forceinline__ void red_add_v2(float* addr, float a, float b) {
    asm volatile("red.global.add.v2.f32 [%0], {%1, %2};"
                 :: "l"(addr), "f"(a), "f"(b));
}
__device__ __forceinline__ float softplus_f(float x) {
    return fmaxf(x, 0.f) + log1pf(expf(-fabsf(x)));
}
__device__ __forceinline__ uint32_t smem_to_u32(const void* p) {
    uint32_t a;
    asm("{ .reg .u64 t; cvta.to.shared.u64 t, %1; cvt.u32.u64 %0, t; }" : "=r"(a) : "l"(p));
    return a;
}
__device__ __forceinline__ void ldm_x4(uint32_t& r0, uint32_t& r1, uint32_t& r2, uint32_t& r3,
                                       uint32_t addr) {
    asm volatile("ldmatrix.sync.aligned.m8n8.x4.shared.b16 {%0,%1,%2,%3}, [%4];"
                 : "=r"(r0), "=r"(r1), "=r"(r2), "=r"(r3) : "r"(addr));
}
__device__ __forceinline__ void ldm_x2(uint32_t& r0, uint32_t& r1, uint32_t addr) {
    asm volatile("ldmatrix.sync.aligned.m8n8.x2.shared.b16 {%0,%1}, [%2];"
                 : "=r"(r0), "=r"(r1) : "r"(addr));
}
__device__ __forceinline__ void mma_bf16(float* c, uint32_t a0, uint32_t a1, uint32_t a2,
                                         uint32_t a3, uint32_t b0, uint32_t b1) {
    asm volatile(
        "mma.sync.aligned.m16n8k16.row.col.f32.bf16.bf16.f32 "
        "{%0,%1,%2,%3}, {%4,%5,%6,%7}, {%8,%9}, {%0,%1,%2,%3};"
        : "+f"(c[0]), "+f"(c[1]), "+f"(c[2]), "+f"(c[3])
        : "r"(a0), "r"(a1), "r"(a2), "r"(a3), "r"(b0), "r"(b1));
}

// ---------------- zero kernels ----------------
__global__ __launch_bounds__(256) void zero1_kernel() {
    int idx = blockIdx.x * 256 + threadIdx.x;
    ((float4*)g_agg1)[idx] = make_float4(0.f, 0.f, 0.f, 0.f);
}
__global__ __launch_bounds__(256) void zero2_kernel() {
    int idx = blockIdx.x * 256 + threadIdx.x;
    ((float4*)g_agg2)[idx] = make_float4(0.f, 0.f, 0.f, 0.f);
}

// ---------------- sort A: relation histogram (1024 edges/block) ----------------
__global__ __launch_bounds__(256) void hist_kernel(const int* __restrict__ et) {
    __shared__ int sh[NRR];
    int tid = threadIdx.x;
    if (tid < NRR) sh[tid] = 0;
    __syncthreads();
    int e0 = blockIdx.x * 1024 + tid;
#pragma unroll
    for (int j = 0; j < 4; j++) atomicAdd(&sh[et[e0 + j * 256]], 1);
    __syncthreads();
    if (tid < NRR && sh[tid]) atomicAdd(&g_hist[tid + 1], sh[tid]);
}

// ---------------- sort B: scan 101 values -> cursors; re-zero hist ----------------
__global__ __launch_bounds__(128) void scan_kernel() {
    __shared__ int s[128];
    int tid = threadIdx.x;
    int v0 = (tid <= NRR) ? g_hist[tid] : 0;
    s[tid] = v0;
    __syncthreads();
#pragma unroll
    for (int d = 1; d < 128; d <<= 1) {
        int v = (tid >= d) ? s[tid - d] : 0;
        __syncthreads();
        s[tid] += v;
        __syncthreads();
    }
    if (tid < NRR) g_cursor[tid] = s[tid];
    if (tid <= NRR) g_hist[tid] = 0;   // ready for next run
}

// ---------------- sort C: block-aggregated scatter; also precompute h[src] -----------
__global__ __launch_bounds__(256) void scatter_kernel(const int* __restrict__ src,
                                                      const int* __restrict__ dst,
                                                      const int* __restrict__ et,
                                                      const float* __restrict__ norm,
                                                      const int* __restrict__ h) {
    __shared__ int cnt[NRR];
    __shared__ int base[NRR];
    int tid = threadIdx.x;
    if (tid < NRR) cnt[tid] = 0;
    __syncthreads();
    int e0 = blockIdx.x * 1024 + tid;
    int r[4], s[4], d[4], nm[4], hs[4];
#pragma unroll
    for (int j = 0; j < 4; j++) {
        int e = e0 + j * 256;
        r[j] = et[e]; s[j] = src[e]; d[j] = dst[e]; nm[j] = __float_as_int(norm[e]);
        hs[j] = h[s[j]];
        atomicAdd(&cnt[r[j]], 1);
    }
    __syncthreads();
    if (tid < NRR) {
        int c = cnt[tid];
        base[tid] = c ? atomicAdd(&g_cursor[tid], c) : 0;
        cnt[tid] = 0;
    }
    __syncthreads();
#pragma unroll
    for (int j = 0; j < 4; j++) {
        int pos = base[r[j]] + atomicAdd(&cnt[r[j]], 1);
        g_recs[pos] = make_int4(s[j], d[j], r[j], nm[j]);
        g_hsrc[pos] = hs[j];
    }
}

// ---------------- layer1 edges: 2 warps per EPW-run (32 bdd blocks each) ----------------
__global__ __launch_bounds__(256) void edge1_kernel(const float* __restrict__ W1,
                                                    const float* __restrict__ embed) {
    int gw = (blockIdx.x * 256 + threadIdx.x) >> 5;
    int lane = threadIdx.x & 31;
    int run = gw >> 1, hf = gw & 1;
    int e0 = run * EPW;
    int b = hf * 32 + lane;
    int cur = -1;
    float4 wv;
    int4 r0 = __ldg(&g_recs[e0]);
    int4 r1 = __ldg(&g_recs[e0 + 1]);
    int hs0 = __ldg(&g_hsrc[e0]), hs1 = __ldg(&g_hsrc[e0 + 1]);
#pragma unroll 1
    for (int e = 0; e < EPW; e += 2) {
        int4 n0 = r0, n1 = r1;
        int m0 = hs0, m1 = hs1;
        if (e + 2 < EPW) {
            n0 = __ldg(&g_recs[e0 + e + 2]);
            n1 = __ldg(&g_recs[e0 + e + 3]);
            m0 = __ldg(&g_hsrc[e0 + e + 2]);
            m1 = __ldg(&g_hsrc[e0 + e + 3]);
        }
        float2 xv0 = ((const float2*)(embed + hs0 * HD))[b];
        float2 xv1 = ((const float2*)(embed + hs1 * HD))[b];
        float nrm0 = __int_as_float(r0.w), nrm1 = __int_as_float(r1.w);
        if (r0.z != cur) {
            wv = __ldg((const float4*)(W1 + r0.z * 256 + b * 4));
            cur = r0.z;
        }
        float a0 = (xv0.x * wv.x + xv0.y * wv.z) * nrm0;
        float a1 = (xv0.x * wv.y + xv0.y * wv.w) * nrm0;
        red_add_v2(g_agg1 + r0.y * HD + b * 2, a0, a1);
        if (r1.z != cur) {
            wv = __ldg((const float4*)(W1 + r1.z * 256 + b * 4));
            cur = r1.z;
        }
        float b0 = (xv1.x * wv.x + xv1.y * wv.z) * nrm1;
        float b1 = (xv1.x * wv.y + xv1.y * wv.w) * nrm1;
        red_add_v2(g_agg1 + r1.y * HD + b * 2, b0, b1);
        r0 = n0; r1 = n1; hs0 = m0; hs1 = m1;
    }
}

// ---------------- sl1 GEMM: tmp1 = embed[h] @ lw1 + b1 (on s2, overlaps sort+edge1) ----
__global__ __launch_bounds__(256) void sl1gemm_kernel(const float* __restrict__ lw1,
                                                      const float* __restrict__ b1,
                                                      const int* __restrict__ h,
                                                      const float* __restrict__ embed) {
    __shared__ float4 ws4[32][32];
    __shared__ float xsh[8][4][33];
    int tid = threadIdx.x;
    int w = tid >> 5, lane = tid & 31;
    int row0 = blockIdx.x * 32 + w * 4;
    int hr_[4];
#pragma unroll
    for (int j = 0; j < 4; j++) hr_[j] = __ldg(&h[row0 + j]);
    unsigned long long acc[4][2];
#pragma unroll
    for (int j = 0; j < 4; j++) { acc[j][0] = 0ULL; acc[j][1] = 0ULL; }
    const float4* lw4 = (const float4*)lw1;
    for (int kc = 0; kc < 4; kc++) {
#pragma unroll
        for (int it = 0; it < 4; it++) {
            int idx = tid + it * 256;
            int k = idx >> 5, c = idx & 31;
            ws4[k][c] = lw4[(kc * 32 + k) * 32 + c];
        }
#pragma unroll
        for (int j = 0; j < 4; j++)
            xsh[w][j][lane] = embed[hr_[j] * HD + kc * 32 + lane];
        __syncthreads();
#pragma unroll
        for (int k = 0; k < 32; k++) {
            float4 wv = ws4[k][lane];
            unsigned long long wlo = pk2(wv.x, wv.y), whi = pk2(wv.z, wv.w);
#pragma unroll
            for (int j = 0; j < 4; j++) {
                float xv = xsh[w][j][k];
                unsigned long long x2 = pk2(xv, xv);
                fma2(acc[j][0], x2, wlo);
                fma2(acc[j][1], x2, whi);
            }
        }
        __syncthreads();
    }
    float4 bv = ((const float4*)b1)[lane];
#pragma unroll
    for (int j = 0; j < 4; j++) {
        float o0, o1, o2, o3;
        upk2(acc[j][0], o0, o1);
        upk2(acc[j][1], o2, o3);
        ((float4*)(g_tmp1 + (row0 + j) * HD))[lane] =
            make_float4(o0 + bv.x, o1 + bv.y, o2 + bv.z, o3 + bv.w);
    }
}

// ---------------- sl1 epilogue: out1 = relu(agg1 + tmp1) ----------------
__global__ __launch_bounds__(256) void sl1epi_kernel() {
    int idx = blockIdx.x * 256 + threadIdx.x;   // float4 index
    float4 a = ((const float4*)g_agg1)[idx];
    float4 t = ((const float4*)g_tmp1)[idx];
    ((float4*)g_out1)[idx] = make_float4(fmaxf(a.x + t.x, 0.f), fmaxf(a.y + t.y, 0.f),
                                         fmaxf(a.z + t.z, 0.f), fmaxf(a.w + t.w, 0.f));
}

// ---------------- layer2 edges: 2 warps per EPW-run (half the 256 cols each) ------------
__global__ __launch_bounds__(256) void edge2_kernel(const float* __restrict__ W2) {
    int gw = (blockIdx.x * 256 + threadIdx.x) >> 5;
    int lane = threadIdx.x & 31;
    int run = gw >> 1, hf = gw & 1;
    int e0 = run * EPW;
    int b = hf * 32 + lane;
    int cur = -1;
    float4 wA, wB;   // W2[r][b][0][0..3], W2[r][b][1][0..3]
    int4 r0 = __ldg(&g_recs[e0]);
    int4 r1 = __ldg(&g_recs[e0 + 1]);
#pragma unroll 1
    for (int e = 0; e < EPW; e += 2) {
        int4 n0 = r0, n1 = r1;
        if (e + 2 < EPW) {
            n0 = __ldg(&g_recs[e0 + e + 2]);
            n1 = __ldg(&g_recs[e0 + e + 3]);
        }
        float2 xv0 = ((const float2*)(g_out1 + r0.x * HD))[b];
        float2 xv1 = ((const float2*)(g_out1 + r1.x * HD))[b];
        float nrm0 = __int_as_float(r0.w), nrm1 = __int_as_float(r1.w);
        if (r0.z != cur) {
            const float4* w4 = (const float4*)(W2 + r0.z * 512 + b * 8);
            wA = __ldg(w4); wB = __ldg(w4 + 1);
            cur = r0.z;
        }
        {
            float o0 = (xv0.x * wA.x + xv0.y * wB.x) * nrm0;
            float o1 = (xv0.x * wA.y + xv0.y * wB.y) * nrm0;
            float o2 = (xv0.x * wA.z + xv0.y * wB.z) * nrm0;
            float o3 = (xv0.x * wA.w + xv0.y * wB.w) * nrm0;
            red_add_v4(g_agg2 + r0.y * 2 * HD + b * 4, o0, o1, o2, o3);
        }
        if (r1.z != cur) {
            const float4* w4 = (const float4*)(W2 + r1.z * 512 + b * 8);
            wA = __ldg(w4); wB = __ldg(w4 + 1);
            cur = r1.z;
        }
        {
            float o0 = (xv1.x * wA.x + xv1.y * wB.x) * nrm1;
            float o1 = (xv1.x * wA.y + xv1.y * wB.y) * nrm1;
            float o2 = (xv1.x * wA.z + xv1.y * wB.z) * nrm1;
            float o3 = (xv1.x * wA.w + xv1.y * wB.w) * nrm1;
            red_add_v4(g_agg2 + r1.y * 2 * HD + b * 4, o0, o1, o2, o3);
        }
        r0 = n0; r1 = n1;
    }
}

// ---------------- sl2 GEMM: tmp2 = out1 @ lw2 + b2 (overlaps edge2) ----------------
__global__ __launch_bounds__(256) void sl2gemm_kernel(const float* __restrict__ lw2,
                                                      const float* __restrict__ b2) {
    __shared__ float4 ws4[32][64];
    __shared__ float xsh[8][4][33];
    int tid = threadIdx.x;
    int w = tid >> 5, lane = tid & 31;
    int row0 = blockIdx.x * 32 + w * 4;
    unsigned long long acc[4][4];
#pragma unroll
    for (int j = 0; j < 4; j++)
#pragma unroll
        for (int g = 0; g < 4; g++) acc[j][g] = 0ULL;
    const float4* lw4 = (const float4*)lw2;
    for (int kc = 0; kc < 4; kc++) {
#pragma unroll
        for (int it = 0; it < 8; it++) {
            int idx = tid + it * 256;
            int k = idx >> 6, c = idx & 63;
            ws4[k][c] = lw4[(kc * 32 + k) * 64 + c];
        }
#pragma unroll
        for (int j = 0; j < 4; j++)
            xsh[w][j][lane] = g_out1[(row0 + j) * HD + kc * 32 + lane];
        __syncthreads();
#pragma unroll
        for (int k = 0; k < 32; k++) {
            float4 w0 = ws4[k][lane];
            float4 w1 = ws4[k][32 + lane];
            unsigned long long wl0 = pk2(w0.x, w0.y), wh0 = pk2(w0.z, w0.w);
            unsigned long long wl1 = pk2(w1.x, w1.y), wh1 = pk2(w1.z, w1.w);
#pragma unroll
            for (int j = 0; j < 4; j++) {
                float xv = xsh[w][j][k];
                unsigned long long x2 = pk2(xv, xv);
                fma2(acc[j][0], x2, wl0);
                fma2(acc[j][1], x2, wh0);
                fma2(acc[j][2], x2, wl1);
                fma2(acc[j][3], x2, wh1);
            }
        }
        __syncthreads();
    }
    float4 b0 = ((const float4*)b2)[lane];
    float4 b1v = ((const float4*)b2)[32 + lane];
#pragma unroll
    for (int j = 0; j < 4; j++) {
        int row = row0 + j;
        float m0, m1, m2, m3, v0, v1, v2, v3;
        upk2(acc[j][0], m0, m1);
        upk2(acc[j][1], m2, m3);
        upk2(acc[j][2], v0, v1);
        upk2(acc[j][3], v2, v3);
        ((float4*)(g_tmp2 + row * 2 * HD))[lane] =
            make_float4(m0 + b0.x, m1 + b0.y, m2 + b0.z, m3 + b0.w);
        ((float4*)(g_tmp2 + row * 2 * HD))[32 + lane] =
            make_float4(v0 + b1v.x, v1 + b1v.y, v2 + b1v.z, v3 + b1v.w);
    }
}

// ---------------- sl2 epilogue: z = m + sqrt(softplus(v)+1e-8)*eps, + bf16 split --------
__global__ __launch_bounds__(256) void sl2epi_kernel(const float* __restrict__ eps) {
    int gid = blockIdx.x * 256 + threadIdx.x;   // 0 .. NN*32-1
    int row = gid >> 5, lane = gid & 31;
    float4 m = ((const float4*)(g_tmp2 + row * 2 * HD))[lane];
    float4 hv = ((const float4*)(g_tmp2 + row * 2 * HD))[32 + lane];
    float4 am = ((const float4*)(g_agg2 + row * 2 * HD))[lane];
    float4 av = ((const float4*)(g_agg2 + row * 2 * HD))[32 + lane];
    float4 ev = ((const float4*)(eps + row * HD))[lane];
    float m0 = m.x + am.x, m1 = m.y + am.y, m2 = m.z + am.z, m3 = m.w + am.w;
    float v0 = hv.x + av.x, v1 = hv.y + av.y, v2 = hv.z + av.z, v3 = hv.w + av.w;
    float z0 = m0 + sqrtf(softplus_f(v0) + 1e-8f) * ev.x;
    float z1 = m1 + sqrtf(softplus_f(v1) + 1e-8f) * ev.y;
    float z2 = m2 + sqrtf(softplus_f(v2) + 1e-8f) * ev.z;
    float z3 = m3 + sqrtf(softplus_f(v3) + 1e-8f) * ev.w;
    ((float4*)(g_z + row * HD))[lane] = make_float4(z0, z1, z2, z3);
    __nv_bfloat16 h0b = __float2bfloat16(z0), h1b = __float2bfloat16(z1);
    __nv_bfloat16 h2b = __float2bfloat16(z2), h3b = __float2bfloat16(z3);
    __nv_bfloat16 l0b = __float2bfloat16(z0 - __bfloat162float(h0b));
    __nv_bfloat16 l1b = __float2bfloat16(z1 - __bfloat162float(h1b));
    __nv_bfloat16 l2b = __float2bfloat16(z2 - __bfloat162float(h2b));
    __nv_bfloat16 l3b = __float2bfloat16(z3 - __bfloat162float(h3b));
    __nv_bfloat162* zh = (__nv_bfloat162*)(g_zhi + row * HD);
    __nv_bfloat162* zl = (__nv_bfloat162*)(g_zlo + row * HD);
    zh[lane * 2]     = __nv_bfloat162(h0b, h1b);
    zh[lane * 2 + 1] = __nv_bfloat162(h2b, h3b);
    zl[lane * 2]     = __nv_bfloat162(l0b, l1b);
    zl[lane * 2 + 1] = __nv_bfloat162(l2b, l3b);
}

// ---------------- hr = z[head_ids] * w_rel[rel_ids], split to bf16 hi/lo ----------------
__global__ __launch_bounds__(256) void hr_kernel(const int* __restrict__ head_ids,
                                                 const int* __restrict__ rel_ids,
                                                 const float* __restrict__ w_rel) {
    int idx = blockIdx.x * blockDim.x + threadIdx.x;  // 0 .. 2048*128-1
    int b = idx >> 7, c = idx & 127;
    float v = g_z[head_ids[b] * HD + c] * w_rel[rel_ids[b] * HD + c];
    __nv_bfloat16 hi = __float2bfloat16(v);
    g_hrhi[idx] = hi;
    g_hrlo[idx] = __float2bfloat16(v - __bfloat162float(hi));
}

// ---------------- decoder via mma.sync bf16 (split-bf16, K-chunked, 2 CTAs/SM) -------
#define TROW 144
#define TILE_SB (128 * TROW)              // 18432 B per tile
#define DEC_SMEM (4 * TILE_SB)            // 73728 B

__global__ __launch_bounds__(256, 2) void decoder_mma_kernel(float* __restrict__ out) {
    extern __shared__ char smem[];
    char* sAhi = smem;
    char* sAlo = smem + TILE_SB;
    char* sBhi = smem + 2 * TILE_SB;
    char* sBlo = smem + 3 * TILE_SB;
    int tid = threadIdx.x;
    int wid = tid >> 5, lane = tid & 31;
    int col0 = blockIdx.x * 128;
    int row0 = blockIdx.y * 128;

    int wr = wid & 1, wc = wid >> 1;
    float acc[4][4][4];
#pragma unroll
    for (int mi = 0; mi < 4; mi++)
#pragma unroll
        for (int ni = 0; ni < 4; ni++)
#pragma unroll
            for (int x = 0; x < 4; x++) acc[mi][ni][x] = 0.f;

    int aRow = wr * 64 + (lane & 7) + ((lane >> 3) & 1) * 8;
    int aKoff = ((lane >> 4) & 1) * 16;
    uint32_t aBaseHi = smem_to_u32(sAhi) + aRow * TROW + aKoff;
    uint32_t aBaseLo = smem_to_u32(sAlo) + aRow * TROW + aKoff;
    int bRow = wc * 32 + (lane & 7);
    int bKoff = ((lane >> 3) & 1) * 16;
    uint32_t bBaseHi = smem_to_u32(sBhi) + bRow * TROW + bKoff;
    uint32_t bBaseLo = smem_to_u32(sBlo) + bRow * TROW + bKoff;

    const __nv_bfloat16* srcs[4] = {g_hrhi, g_hrlo, g_zhi, g_zlo};
    char* dsts[4] = {sAhi, sAlo, sBhi, sBlo};

#pragma unroll 1
    for (int kc = 0; kc < 2; kc++) {
#pragma unroll
        for (int t = 0; t < 4; t++) {
            bool isB = (t >= 2);
            const __nv_bfloat16* src = srcs[t];
            char* dst = dsts[t];
#pragma unroll
            for (int it = 0; it < 4; it++) {
                int idx = tid + it * 256;
                int r = idx >> 3, q = idx & 7;
                uint4 v = make_uint4(0u, 0u, 0u, 0u);
                int grow = (isB ? col0 : row0) + r;
                if (!isB || grow < NN)
                    v = *(const uint4*)(src + grow * HD + kc * 64 + q * 8);
                *(uint4*)(dst + r * TROW + q * 16) = v;
            }
        }
        __syncthreads();

#pragma unroll
        for (int ks = 0; ks < 4; ks++) {
            int ko = ks * 32;
            uint32_t bh[4][2], bl[4][2];
#pragma unroll
            for (int ni = 0; ni < 4; ni++) {
                ldm_x2(bh[ni][0], bh[ni][1], bBaseHi + ni * 8 * TROW + ko);
                ldm_x2(bl[ni][0], bl[ni][1], bBaseLo + ni * 8 * TROW + ko);
            }
#pragma unroll
            for (int mi = 0; mi < 4; mi++) {
                uint32_t ah0, ah1, ah2, ah3, al0, al1, al2, al3;
                ldm_x4(ah0, ah1, ah2, ah3, aBaseHi + mi * 16 * TROW + ko);
                ldm_x4(al0, al1, al2, al3, aBaseLo + mi * 16 * TROW + ko);
#pragma unroll
                for (int ni = 0; ni < 4; ni++) {
                    mma_bf16(acc[mi][ni], ah0, ah1, ah2, ah3, bh[ni][0], bh[ni][1]);
                    mma_bf16(acc[mi][ni], ah0, ah1, ah2, ah3, bl[ni][0], bl[ni][1]);
                    mma_bf16(acc[mi][ni], al0, al1, al2, al3, bh[ni][0], bh[ni][1]);
                }
            }
        }
        __syncthreads();
    }

#pragma unroll
    for (int mi = 0; mi < 4; mi++) {
        int rgA = row0 + wr * 64 + mi * 16 + (lane >> 2);
        float* orow0 = out + (size_t)rgA * NN;
        float* orow1 = out + (size_t)(rgA + 8) * NN;
#pragma unroll
        for (int ni = 0; ni < 4; ni++) {
            int cg = col0 + wc * 32 + ni * 8 + (lane & 3) * 2;
            if (cg < NN) {
                *(float2*)(orow0 + cg) = make_float2(acc[mi][ni][0], acc[mi][ni][1]);
                *(float2*)(orow1 + cg) = make_float2(acc[mi][ni][2], acc[mi][ni][3]);
            }
        }
    }
}

// ---------------- launch: capture-forked streams, edge1 ∥ sl1gemm ----------------
extern "C" void kernel_launch(void* const* d_in, const int* in_sizes, int n_in,
                              void* d_out, int out_size) {
    const int*   h        = (const int*)d_in[0];
    const int*   src      = (const int*)d_in[1];
    const int*   dst      = (const int*)d_in[2];
    const int*   etypes   = (const int*)d_in[3];
    const float* norm     = (const float*)d_in[4];
    const int*   head_ids = (const int*)d_in[5];
    const int*   rel_ids  = (const int*)d_in[6];
    const float* embed    = (const float*)d_in[7];
    const float* W1       = (const float*)d_in[8];
    const float* lw1      = (const float*)d_in[9];
    const float* b1       = (const float*)d_in[10];
    const float* W2       = (const float*)d_in[11];
    const float* lw2      = (const float*)d_in[12];
    const float* b2       = (const float*)d_in[13];
    const float* w_rel    = (const float*)d_in[14];
    const float* eps      = (const float*)d_in[15];
    float* out = (float*)d_out;

    static cudaStream_t s1 = nullptr, s2 = nullptr;
    static cudaEvent_t eFork, eSort, eG1, eEpi1, eG2;
    if (!s1) {
        cudaStreamCreateWithFlags(&s1, cudaStreamNonBlocking);
        cudaStreamCreateWithFlags(&s2, cudaStreamNonBlocking);
        cudaEventCreateWithFlags(&eFork, cudaEventDisableTiming);
        cudaEventCreateWithFlags(&eSort, cudaEventDisableTiming);
        cudaEventCreateWithFlags(&eG1, cudaEventDisableTiming);
        cudaEventCreateWithFlags(&eEpi1, cudaEventDisableTiming);
        cudaEventCreateWithFlags(&eG2, cudaEventDisableTiming);
        cudaFuncSetAttribute(decoder_mma_kernel,
                             cudaFuncAttributeMaxDynamicSharedMemorySize, DEC_SMEM);
    }

    // fork: sort+zeroes on s1, sl1gemm on s2 (starts immediately), edge1 on main
    cudaEventRecord(eFork, 0);
    cudaStreamWaitEvent(s1, eFork, 0);
    cudaStreamWaitEvent(s2, eFork, 0);

    hist_kernel<<<EE / 1024, 256, 0, s1>>>(etypes);
    scan_kernel<<<1, 128, 0, s1>>>();
    scatter_kernel<<<EE / 1024, 256, 0, s1>>>(src, dst, etypes, norm, h);
    zero1_kernel<<<(NN * HD / 4) / 256, 256, 0, s1>>>();
    zero2_kernel<<<(NN * 2 * HD / 4) / 256, 256, 0, s1>>>();
    cudaEventRecord(eSort, s1);

    sl1gemm_kernel<<<NN / 32, 256, 0, s2>>>(lw1, b1, h, embed);
    cudaEventRecord(eG1, s2);

    // edge1 on main — starts as soon as sort+zero1 land; overlaps sl1gemm on s2
    cudaStreamWaitEvent(0, eSort, 0);
    edge1_kernel<<<(EE * 2) / (EPW * 8), 256>>>(W1, embed);

    // join, epilogue 1
    cudaStreamWaitEvent(0, eG1, 0);
    sl1epi_kernel<<<(NN * HD / 4) / 256, 256>>>();
    cudaEventRecord(eEpi1, 0);

    // sl2 GEMM on s2, edge2 on main (both read out1)
    cudaStreamWaitEvent(s2, eEpi1, 0);
    sl2gemm_kernel<<<NN / 32, 256, 0, s2>>>(lw2, b2);
    cudaEventRecord(eG2, s2);

    edge2_kernel<<<(EE * 2) / (EPW * 8), 256>>>(W2);

    // join, epilogue 2 + tail
    cudaStreamWaitEvent(0, eG2, 0);
    sl2epi_kernel<<<(NN * 32) / 256, 256>>>(eps);
    hr_kernel<<<(2048 * HD) / 256, 256>>>(head_ids, rel_ids, w_rel);
    dim3 dgrid((NN + 127) / 128, 2048 / 128);
    decoder_mma_kernel<<<dgrid, 256, DEC_SMEM>>>(out);
}